// round 12
// baseline (speedup 1.0000x reference)
#include <cuda_runtime.h>

// knnLoss: single persistent kernel. x-counting-sort, fixed 3072-target window
// per 256-query sorted chunk (2-way split), smem FFMA2 inner loop, conservative
// coverage check + exact full-scan fallback, deterministic fixed-point reduce.

#define NPTS   16384
#define NB     2
#define NQ     (NB * NPTS)
#define NBINS  512
#define XMIN   (-4.5f)
#define BINSCL (NBINS / 9.0f)
#define WBIN   (9.0f / NBINS)
#define NTHR   256
#define NBLK   256
#define WIN    3072
#define HWIN   (WIN / 2)         // per-split span 1536
#define TILEW  512
#define NTILE  (HWIN / TILEW)    // 3

__device__ int g_thist[NB * NBINS];
__device__ int g_qhist[NB * NBINS];
__device__ int g_tbase[NB * NBINS];
__device__ int g_tcur [NB * NBINS];
__device__ int g_qcur [NB * NBINS];
__device__ __align__(16) float g_sx[NQ];
__device__ __align__(16) float g_sy[NQ];
__device__ __align__(16) float g_sz[NQ];
__device__ __align__(16) float g_sw[NQ];
__device__ float4    g_q[NQ];
__device__ float     g_part[2 * NQ * 3];
__device__ float     g_d[NQ];
__device__ int       g_fb[NQ];
__device__ int       g_fbn;
__device__ long long g_psum[128];
__device__ int       g_pcnt[128];
__device__ unsigned          g_barcnt;
__device__ volatile unsigned g_bargen;

#define FMA2(d, a, b, c) \
    asm("fma.rn.f32x2 %0, %1, %2, %3;" : "=l"(d) : "l"(a), "l"(b), "l"(c))
#define UNPK2(lo, hi, v) \
    asm("mov.b64 {%0, %1}, %2;" : "=f"(lo), "=f"(hi) : "l"(v))
#define DUP2(d, f) \
    asm("mov.b64 %0, {%1, %1};" : "=l"(d) : "f"(f))

__device__ __forceinline__ void grid_sync() {
    __syncthreads();
    if (threadIdx.x == 0) {
        unsigned gen = g_bargen;
        __threadfence();
        unsigned rank = atomicAdd(&g_barcnt, 1u);
        if (rank == NBLK - 1) {
            g_barcnt = 0;
            __threadfence();
            g_bargen = gen + 1;
        } else {
            while (g_bargen == gen) { __nanosleep(128); }
        }
        __threadfence();
    }
    __syncthreads();
}

__device__ __forceinline__ int xbin(float x) {
    int b = (int)((x - XMIN) * BINSCL);
    return min(max(b, 0), NBINS - 1);
}

__device__ __forceinline__ void top3_insert(float r, float& b0, float& b1, float& b2) {
    float m1 = fmaxf(r, b1);
    float m0 = fmaxf(r, b0);
    b2 = fminf(b2, m1);
    b1 = fminf(b1, m0);
    b0 = fminf(b0, r);
}

__global__ __launch_bounds__(NTHR, 2) void fused_kernel(
    const float* __restrict__ src, const float* __restrict__ tgt,
    float* __restrict__ out)
{
    __shared__ ulonglong2 s_x[TILEW / 4], s_y[TILEW / 4];
    __shared__ ulonglong2 s_z[TILEW / 4], s_w[TILEW / 4];
    __shared__ int        scan[NBINS];
    __shared__ float      fb3[NTHR * 3];
    __shared__ long long  wsum[NTHR / 32];
    __shared__ int        wcnt[NTHR / 32];
    __shared__ long long  rs[128];
    __shared__ int        rc[128];

    int tid  = threadIdx.x;
    int bid  = blockIdx.x;
    int gi   = bid * NTHR + tid;
    int lane = tid & 31;
    int warp = tid >> 5;

    // ---- phase 0: zero hists + fallback counter ----
    if (gi < NB * NBINS)           g_thist[gi] = 0;
    else if (gi < 2 * NB * NBINS)  g_qhist[gi - NB * NBINS] = 0;
    if (gi == 0) g_fbn = 0;
    grid_sync();

    // input decode (phases 1 & 3); valid only for gi < NB*NPTS
    int pb = gi >> 14;
    int pn = gi & (NPTS - 1);
    int ph = pn >> 9;
    int pw = pn & 511;
    long sOff = (((long)pb * 64 + 2 * ph) * 2048 + 4 * pw) * 3;
    long tOff = (long)pb * 3 * 64 * 2048 + (long)(2 * ph) * 2048 + 4 * pw;

    // ---- phase 1: histogram ----
    if (gi < NB * NPTS) {
        float sxv = src[sOff];
        float txv = tgt[tOff];
        atomicAdd(&g_thist[pb * NBINS + xbin(txv)], 1);
        atomicAdd(&g_qhist[pb * NBINS + xbin(sxv)], 1);
    }
    grid_sync();

    // ---- phase 2: prefix sums (blocks 0..3, one array each) ----
    if (bid < 4) {
        const int* h = (bid < 2) ? (g_thist + bid * NBINS)
                                 : (g_qhist + (bid - 2) * NBINS);
        int o0 = __ldcg(h + tid);
        int o1 = __ldcg(h + tid + NTHR);
        scan[tid] = o0;
        scan[tid + NTHR] = o1;
        __syncthreads();
        for (int off = 1; off < NBINS; off <<= 1) {
            int v0 = (tid >= off) ? scan[tid - off] : 0;
            int v1 = (tid + NTHR >= off) ? scan[tid + NTHR - off] : 0;
            __syncthreads();
            scan[tid] += v0;
            scan[tid + NTHR] += v1;
            __syncthreads();
        }
        int e0 = scan[tid] - o0;
        int e1 = scan[tid + NTHR] - o1;
        if (bid < 2) {
            g_tbase[bid * NBINS + tid] = e0;
            g_tbase[bid * NBINS + tid + NTHR] = e1;
            g_tcur [bid * NBINS + tid] = e0;
            g_tcur [bid * NBINS + tid + NTHR] = e1;
        } else {
            g_qcur[(bid - 2) * NBINS + tid] = e0;
            g_qcur[(bid - 2) * NBINS + tid + NTHR] = e1;
        }
    }
    grid_sync();

    // ---- phase 3: counting scatter ----
    if (gi < NB * NPTS) {
        float tx = tgt[tOff];
        float ty = tgt[tOff + 64 * 2048];
        float tz = tgt[tOff + 2L * 64 * 2048];
        bool  vt = (tx != 0.0f) || (ty != 0.0f) || (tz != 0.0f);
        float tw;
        if (vt) tw = tx * tx + ty * ty + tz * tz;
        else { tx = 0.0f; ty = 0.0f; tz = 0.0f; tw = 1e20f; }
        int tpos = atomicAdd(&g_tcur[pb * NBINS + xbin(tx)], 1);
        int ts = pb * NPTS + tpos;
        g_sx[ts] = tx; g_sy[ts] = ty; g_sz[ts] = tz; g_sw[ts] = tw;

        float sxv = src[sOff + 0];
        float syv = src[sOff + 1];
        float szv = src[sOff + 2];
        bool  vs = (sxv != 0.0f) || (syv != 0.0f) || (szv != 0.0f);
        float sq2 = sxv * sxv + syv * syv + szv * szv;
        int qpos = atomicAdd(&g_qcur[pb * NBINS + xbin(sxv)], 1);
        g_q[pb * NPTS + qpos] = make_float4(-2.0f * sxv, -2.0f * syv, -2.0f * szv,
                                            vs ? sq2 : -1.0f);
    }
    grid_sync();

    // ---- phase 4: fixed-window scan (all 256 blocks; 2 splits per chunk) ----
    {
        int chunk = bid >> 1;                  // 0..127
        int sp    = bid & 1;
        int b     = chunk >> 6;
        int qbase = b * NPTS + (chunk & 63) * NTHR;
        int qid   = qbase + tid;

        float4 s = g_q[qid];
        unsigned long long qx, qy, qz;
        DUP2(qx, s.x); DUP2(qy, s.y); DUP2(qz, s.z);

        float xc  = -0.5f * __ldcg(&g_q[qbase + 128].x);
        int  pos  = __ldcg(&g_tbase[b * NBINS + xbin(xc)]);
        int  winLo = min(max(pos - HWIN, 0), NPTS - WIN) & ~3;
        int  segLo = winLo + sp * HWIN;

        float b0 = 3e38f, b1 = 3e38f, b2 = 3e38f;

        for (int t = 0; t < NTILE; t++) {
            int gbase = b * NPTS + segLo + t * TILEW;
            const float4* px = (const float4*)(g_sx + gbase);
            const float4* py = (const float4*)(g_sy + gbase);
            const float4* pz = (const float4*)(g_sz + gbase);
            const float4* pw2 = (const float4*)(g_sw + gbase);
            if (tid < TILEW / 4) {
                float4 vx = px[tid]; s_x[tid] = *(const ulonglong2*)&vx;
                float4 vy = py[tid]; s_y[tid] = *(const ulonglong2*)&vy;
            } else if (tid < TILEW / 2) {
                int i2 = tid - TILEW / 4;
                float4 vz = pz[i2]; s_z[i2] = *(const ulonglong2*)&vz;
                float4 vw = pw2[i2]; s_w[i2] = *(const ulonglong2*)&vw;
            }
            __syncthreads();

#pragma unroll 4
            for (int j = 0; j < TILEW / 4; j++) {
                ulonglong2 xv = s_x[j];
                ulonglong2 yv = s_y[j];
                ulonglong2 zv = s_z[j];
                ulonglong2 wv = s_w[j];
                unsigned long long rA, rB;
                FMA2(rA, qx, xv.x, wv.x);
                FMA2(rB, qx, xv.y, wv.y);
                FMA2(rA, qy, yv.x, rA);
                FMA2(rB, qy, yv.y, rB);
                FMA2(rA, qz, zv.x, rA);
                FMA2(rB, qz, zv.y, rB);
                float r0, r1, r2, r3;
                UNPK2(r0, r1, rA);
                UNPK2(r2, r3, rB);
                float m = fminf(fminf(r0, r1), fminf(r2, r3));
                if (m < b2) {
                    top3_insert(r0, b0, b1, b2);
                    top3_insert(r1, b0, b1, b2);
                    top3_insert(r2, b0, b1, b2);
                    top3_insert(r3, b0, b1, b2);
                }
            }
            __syncthreads();
        }

        int o = (sp * NQ + qid) * 3;
        g_part[o + 0] = b0;
        g_part[o + 1] = b1;
        g_part[o + 2] = b2;
    }
    grid_sync();

    // ---- phase 5: merge + coverage check (blocks 0..127) ----
    if (bid < 128) {
        int chunk = bid;
        int b     = chunk >> 6;
        int qbase = b * NPTS + (chunk & 63) * NTHR;
        int qid   = qbase + tid;

        float4 s  = g_q[qid];
        float  xq = -0.5f * s.x;
        bool   valid = (s.w >= 0.0f);
        float  sq = fmaxf(s.w, 0.0f);

        float b0 = 3e38f, b1 = 3e38f, b2 = 3e38f;
#pragma unroll
        for (int sp = 0; sp < 2; sp++) {
            int o = (sp * NQ + qid) * 3;
            top3_insert(__ldcg(&g_part[o + 0]), b0, b1, b2);
            top3_insert(__ldcg(&g_part[o + 1]), b0, b1, b2);
            top3_insert(__ldcg(&g_part[o + 2]), b0, b1, b2);
        }

        float xc  = -0.5f * g_q[qbase + 128].x;
        int  pos  = g_tbase[b * NBINS + xbin(xc)];
        int  winLo = min(max(pos - HWIN, 0), NPTS - WIN) & ~3;

        float rq = sqrtf(fmaxf(b2 + sq, 0.0f));
        // excluded left: bins <= bin(x[winLo])  -> x <= binCeil
        // excluded right: bins >= bin(x[winLo+WIN-1]) -> x >= binFloor
        bool okL = (winLo == 0);
        if (!okL) {
            int bl = xbin(g_sx[b * NPTS + winLo]);
            okL = (xq - rq) >= (XMIN + (bl + 1) * WBIN);
        }
        bool okR = (winLo + WIN >= NPTS);
        if (!okR) {
            int br = xbin(g_sx[b * NPTS + winLo + WIN - 1]);
            okR = (xq + rq) <= (XMIN + br * WBIN);
        }

        if (valid && !(okL && okR)) {
            int fi = atomicAdd(&g_fbn, 1);
            g_fb[fi] = qid;
        } else {
            float dsum = sqrtf(fmaxf(b0 + sq, 0.0f))
                       + sqrtf(fmaxf(b1 + sq, 0.0f))
                       + sqrtf(fmaxf(b2 + sq, 0.0f));
            g_d[qid] = valid ? dsum : 0.0f;
        }
    }
    grid_sync();

    // ---- phase 6: exact full-scan fallback (rare) ----
    {
        int nfb = __ldcg(&g_fbn);
        for (int fi = bid; fi < nfb; fi += NBLK) {
            int qid = __ldcg(&g_fb[fi]);
            float4 ms = g_q[qid];
            float  msq = fmaxf(ms.w, 0.0f);
            int    mb  = qid >> 14;
            const float* bx = g_sx + mb * NPTS;
            const float* by = g_sy + mb * NPTS;
            const float* bz = g_sz + mb * NPTS;
            const float* bw = g_sw + mb * NPTS;

            float b0 = 3e38f, b1 = 3e38f, b2 = 3e38f;
            int beg = tid * (NPTS / NTHR);
            for (int k = 0; k < NPTS / NTHR; k++) {
                int i = beg + k;
                float r = fmaf(ms.x, bx[i], bw[i]);
                r = fmaf(ms.y, by[i], r);
                r = fmaf(ms.z, bz[i], r);
                top3_insert(r, b0, b1, b2);
            }
            fb3[tid * 3 + 0] = b0;
            fb3[tid * 3 + 1] = b1;
            fb3[tid * 3 + 2] = b2;
            __syncthreads();
            if (tid == 0) {
                float c0 = 3e38f, c1 = 3e38f, c2 = 3e38f;
                for (int i = 0; i < NTHR * 3; i++)
                    top3_insert(fb3[i], c0, c1, c2);
                float dsum = sqrtf(fmaxf(c0 + msq, 0.0f))
                           + sqrtf(fmaxf(c1 + msq, 0.0f))
                           + sqrtf(fmaxf(c2 + msq, 0.0f));
                g_d[qid] = dsum;
            }
            __syncthreads();
        }
    }
    grid_sync();

    // ---- phase 7: deterministic fixed-point reduce ----
    if (bid < 128) {
        int qid = bid * NTHR + tid;               // batch = qid >> 14
        bool valid = (g_q[qid].w >= 0.0f);
        float d = __ldcg(&g_d[qid]);
        long long v = __float2ll_rn(fminf(d, 1e5f) * 4294967296.0f);
#pragma unroll
        for (int o = 16; o; o >>= 1)
            v += __shfl_down_sync(0xffffffffu, v, o);
        int cnt = __popc(__ballot_sync(0xffffffffu, valid));
        if (lane == 0) { wsum[warp] = v; wcnt[warp] = cnt; }
        __syncthreads();
        if (tid == 0) {
            long long vs = 0; int cs = 0;
#pragma unroll
            for (int i = 0; i < NTHR / 32; i++) { vs += wsum[i]; cs += wcnt[i]; }
            g_psum[bid] = vs;
            g_pcnt[bid] = cs;
        }
    }
    grid_sync();

    if (bid == 0) {
        if (tid < 128) {
            rs[tid] = __ldcg(&g_psum[tid]);
            rc[tid] = __ldcg(&g_pcnt[tid]);
        }
        __syncthreads();
        for (int o = 32; o; o >>= 1) {
            if (tid < o) { rs[tid] += rs[tid + o]; rc[tid] += rc[tid + o]; }
            else if (tid >= 64 && tid < 64 + o) {
                rs[tid] += rs[tid + o]; rc[tid] += rc[tid + o];
            }
            __syncthreads();
        }
        if (tid == 0) {
            double S0 = (double)rs[0]  / 4294967296.0;
            double S1 = (double)rs[64] / 4294967296.0;
            float l0 = (float)(S0 / (3.0 * (double)max(rc[0],  1)));
            float l1 = (float)(S1 / (3.0 * (double)max(rc[64], 1)));
            out[0] = 0.5f * (l0 + l1);
        }
    }
}

extern "C" void kernel_launch(void* const* d_in, const int* in_sizes, int n_in,
                              void* d_out, int out_size) {
    const float* src = (const float*)d_in[0];   // source_pc [2,64,2048,3]
    const float* tgt = (const float*)d_in[1];   // target_pc [2,3,64,2048]
    fused_kernel<<<NBLK, NTHR>>>(src, tgt, (float*)d_out);
}

// round 13
// speedup vs baseline: 1.0069x; 1.0069x over previous
#include <cuda_runtime.h>

// knnLoss: single persistent kernel. x-counting-sort, fixed 3072-target window
// per 256-query sorted chunk (2-way split), smem FFMA2 inner loop, conservative
// coverage check + exact full-scan fallback, deterministic fixed-point reduce.

#define NPTS   16384
#define NB     2
#define NQ     (NB * NPTS)
#define NBINS  512
#define XMIN   (-4.5f)
#define BINSCL (NBINS / 9.0f)
#define WBIN   (9.0f / NBINS)
#define NTHR   256
#define NBLK   256
#define WIN    3072
#define HWIN   (WIN / 2)         // per-split span 1536
#define TILEW  512
#define NTILE  (HWIN / TILEW)    // 3

__device__ int g_thist[NB * NBINS];
__device__ int g_qhist[NB * NBINS];
__device__ int g_tbase[NB * NBINS];
__device__ int g_tcur [NB * NBINS];
__device__ int g_qcur [NB * NBINS];
__device__ __align__(16) float g_sx[NQ];
__device__ __align__(16) float g_sy[NQ];
__device__ __align__(16) float g_sz[NQ];
__device__ __align__(16) float g_sw[NQ];
__device__ float4    g_q[NQ];
__device__ float     g_part[2 * NQ * 3];
__device__ float     g_d[NQ];
__device__ int       g_fb[NQ];
__device__ int       g_fbn;
__device__ long long g_psum[128];
__device__ int       g_pcnt[128];
__device__ unsigned          g_barcnt;
__device__ volatile unsigned g_bargen;

#define FMA2(d, a, b, c) \
    asm("fma.rn.f32x2 %0, %1, %2, %3;" : "=l"(d) : "l"(a), "l"(b), "l"(c))
#define UNPK2(lo, hi, v) \
    asm("mov.b64 {%0, %1}, %2;" : "=f"(lo), "=f"(hi) : "l"(v))
#define DUP2(d, f) \
    asm("mov.b64 %0, {%1, %1};" : "=l"(d) : "f"(f))

__device__ __forceinline__ void grid_sync() {
    __syncthreads();
    if (threadIdx.x == 0) {
        unsigned gen = g_bargen;
        __threadfence();
        unsigned rank = atomicAdd(&g_barcnt, 1u);
        if (rank == NBLK - 1) {
            g_barcnt = 0;
            __threadfence();
            g_bargen = gen + 1;
        } else {
            while (g_bargen == gen) { __nanosleep(128); }
        }
        __threadfence();
    }
    __syncthreads();
}

__device__ __forceinline__ int xbin(float x) {
    int b = (int)((x - XMIN) * BINSCL);
    return min(max(b, 0), NBINS - 1);
}

__device__ __forceinline__ void top3_insert(float r, float& b0, float& b1, float& b2) {
    float m1 = fmaxf(r, b1);
    float m0 = fmaxf(r, b0);
    b2 = fminf(b2, m1);
    b1 = fminf(b1, m0);
    b0 = fminf(b0, r);
}

__global__ __launch_bounds__(NTHR, 2) void fused_kernel(
    const float* __restrict__ src, const float* __restrict__ tgt,
    float* __restrict__ out)
{
    __shared__ ulonglong2 s_x[TILEW / 4], s_y[TILEW / 4];
    __shared__ ulonglong2 s_z[TILEW / 4], s_w[TILEW / 4];
    __shared__ int        scan[NBINS];
    __shared__ float      fb3[NTHR * 3];
    __shared__ long long  wsum[NTHR / 32];
    __shared__ int        wcnt[NTHR / 32];
    __shared__ long long  rs[128];
    __shared__ int        rc[128];

    int tid  = threadIdx.x;
    int bid  = blockIdx.x;
    int gi   = bid * NTHR + tid;
    int lane = tid & 31;
    int warp = tid >> 5;

    // ---- phase 0: zero hists + fallback counter ----
    if (gi < NB * NBINS)           g_thist[gi] = 0;
    else if (gi < 2 * NB * NBINS)  g_qhist[gi - NB * NBINS] = 0;
    if (gi == 0) g_fbn = 0;
    grid_sync();

    // input decode (phases 1 & 3); valid only for gi < NB*NPTS
    int pb = gi >> 14;
    int pn = gi & (NPTS - 1);
    int ph = pn >> 9;
    int pw = pn & 511;
    long sOff = (((long)pb * 64 + 2 * ph) * 2048 + 4 * pw) * 3;
    long tOff = (long)pb * 3 * 64 * 2048 + (long)(2 * ph) * 2048 + 4 * pw;

    // ---- phase 1: histogram ----
    if (gi < NB * NPTS) {
        float sxv = src[sOff];
        float txv = tgt[tOff];
        atomicAdd(&g_thist[pb * NBINS + xbin(txv)], 1);
        atomicAdd(&g_qhist[pb * NBINS + xbin(sxv)], 1);
    }
    grid_sync();

    // ---- phase 2: prefix sums (blocks 0..3, one array each) ----
    if (bid < 4) {
        const int* h = (bid < 2) ? (g_thist + bid * NBINS)
                                 : (g_qhist + (bid - 2) * NBINS);
        int o0 = __ldcg(h + tid);
        int o1 = __ldcg(h + tid + NTHR);
        scan[tid] = o0;
        scan[tid + NTHR] = o1;
        __syncthreads();
        for (int off = 1; off < NBINS; off <<= 1) {
            int v0 = (tid >= off) ? scan[tid - off] : 0;
            int v1 = (tid + NTHR >= off) ? scan[tid + NTHR - off] : 0;
            __syncthreads();
            scan[tid] += v0;
            scan[tid + NTHR] += v1;
            __syncthreads();
        }
        int e0 = scan[tid] - o0;
        int e1 = scan[tid + NTHR] - o1;
        if (bid < 2) {
            g_tbase[bid * NBINS + tid] = e0;
            g_tbase[bid * NBINS + tid + NTHR] = e1;
            g_tcur [bid * NBINS + tid] = e0;
            g_tcur [bid * NBINS + tid + NTHR] = e1;
        } else {
            g_qcur[(bid - 2) * NBINS + tid] = e0;
            g_qcur[(bid - 2) * NBINS + tid + NTHR] = e1;
        }
    }
    grid_sync();

    // ---- phase 3: counting scatter ----
    if (gi < NB * NPTS) {
        float tx = tgt[tOff];
        float ty = tgt[tOff + 64 * 2048];
        float tz = tgt[tOff + 2L * 64 * 2048];
        bool  vt = (tx != 0.0f) || (ty != 0.0f) || (tz != 0.0f);
        float tw;
        if (vt) tw = tx * tx + ty * ty + tz * tz;
        else { tx = 0.0f; ty = 0.0f; tz = 0.0f; tw = 1e20f; }
        int tpos = atomicAdd(&g_tcur[pb * NBINS + xbin(tx)], 1);
        int ts = pb * NPTS + tpos;
        g_sx[ts] = tx; g_sy[ts] = ty; g_sz[ts] = tz; g_sw[ts] = tw;

        float sxv = src[sOff + 0];
        float syv = src[sOff + 1];
        float szv = src[sOff + 2];
        bool  vs = (sxv != 0.0f) || (syv != 0.0f) || (szv != 0.0f);
        float sq2 = sxv * sxv + syv * syv + szv * szv;
        int qpos = atomicAdd(&g_qcur[pb * NBINS + xbin(sxv)], 1);
        g_q[pb * NPTS + qpos] = make_float4(-2.0f * sxv, -2.0f * syv, -2.0f * szv,
                                            vs ? sq2 : -1.0f);
    }
    grid_sync();

    // ---- phase 4: fixed-window scan (all 256 blocks; 2 splits per chunk) ----
    {
        int chunk = bid >> 1;                  // 0..127
        int sp    = bid & 1;
        int b     = chunk >> 6;
        int qbase = b * NPTS + (chunk & 63) * NTHR;
        int qid   = qbase + tid;

        float4 s = g_q[qid];
        unsigned long long qx, qy, qz;
        DUP2(qx, s.x); DUP2(qy, s.y); DUP2(qz, s.z);

        float xc  = -0.5f * __ldcg(&g_q[qbase + 128].x);
        int  pos  = __ldcg(&g_tbase[b * NBINS + xbin(xc)]);
        int  winLo = min(max(pos - HWIN, 0), NPTS - WIN) & ~3;
        int  segLo = winLo + sp * HWIN;

        float b0 = 3e38f, b1 = 3e38f, b2 = 3e38f;

        for (int t = 0; t < NTILE; t++) {
            int gbase = b * NPTS + segLo + t * TILEW;
            const float4* px = (const float4*)(g_sx + gbase);
            const float4* py = (const float4*)(g_sy + gbase);
            const float4* pz = (const float4*)(g_sz + gbase);
            const float4* pw2 = (const float4*)(g_sw + gbase);
            if (tid < TILEW / 4) {
                float4 vx = px[tid]; s_x[tid] = *(const ulonglong2*)&vx;
                float4 vy = py[tid]; s_y[tid] = *(const ulonglong2*)&vy;
            } else if (tid < TILEW / 2) {
                int i2 = tid - TILEW / 4;
                float4 vz = pz[i2]; s_z[i2] = *(const ulonglong2*)&vz;
                float4 vw = pw2[i2]; s_w[i2] = *(const ulonglong2*)&vw;
            }
            __syncthreads();

#pragma unroll 4
            for (int j = 0; j < TILEW / 4; j++) {
                ulonglong2 xv = s_x[j];
                ulonglong2 yv = s_y[j];
                ulonglong2 zv = s_z[j];
                ulonglong2 wv = s_w[j];
                unsigned long long rA, rB;
                FMA2(rA, qx, xv.x, wv.x);
                FMA2(rB, qx, xv.y, wv.y);
                FMA2(rA, qy, yv.x, rA);
                FMA2(rB, qy, yv.y, rB);
                FMA2(rA, qz, zv.x, rA);
                FMA2(rB, qz, zv.y, rB);
                float r0, r1, r2, r3;
                UNPK2(r0, r1, rA);
                UNPK2(r2, r3, rB);
                float m = fminf(fminf(r0, r1), fminf(r2, r3));
                if (m < b2) {
                    top3_insert(r0, b0, b1, b2);
                    top3_insert(r1, b0, b1, b2);
                    top3_insert(r2, b0, b1, b2);
                    top3_insert(r3, b0, b1, b2);
                }
            }
            __syncthreads();
        }

        int o = (sp * NQ + qid) * 3;
        g_part[o + 0] = b0;
        g_part[o + 1] = b1;
        g_part[o + 2] = b2;
    }
    grid_sync();

    // ---- phase 5: merge + coverage check (blocks 0..127) ----
    if (bid < 128) {
        int chunk = bid;
        int b     = chunk >> 6;
        int qbase = b * NPTS + (chunk & 63) * NTHR;
        int qid   = qbase + tid;

        float4 s  = g_q[qid];
        float  xq = -0.5f * s.x;
        bool   valid = (s.w >= 0.0f);
        float  sq = fmaxf(s.w, 0.0f);

        float b0 = 3e38f, b1 = 3e38f, b2 = 3e38f;
#pragma unroll
        for (int sp = 0; sp < 2; sp++) {
            int o = (sp * NQ + qid) * 3;
            top3_insert(__ldcg(&g_part[o + 0]), b0, b1, b2);
            top3_insert(__ldcg(&g_part[o + 1]), b0, b1, b2);
            top3_insert(__ldcg(&g_part[o + 2]), b0, b1, b2);
        }

        float xc  = -0.5f * g_q[qbase + 128].x;
        int  pos  = g_tbase[b * NBINS + xbin(xc)];
        int  winLo = min(max(pos - HWIN, 0), NPTS - WIN) & ~3;

        float rq = sqrtf(fmaxf(b2 + sq, 0.0f));
        // excluded left: bins <= bin(x[winLo])  -> x <= binCeil
        // excluded right: bins >= bin(x[winLo+WIN-1]) -> x >= binFloor
        bool okL = (winLo == 0);
        if (!okL) {
            int bl = xbin(g_sx[b * NPTS + winLo]);
            okL = (xq - rq) >= (XMIN + (bl + 1) * WBIN);
        }
        bool okR = (winLo + WIN >= NPTS);
        if (!okR) {
            int br = xbin(g_sx[b * NPTS + winLo + WIN - 1]);
            okR = (xq + rq) <= (XMIN + br * WBIN);
        }

        if (valid && !(okL && okR)) {
            int fi = atomicAdd(&g_fbn, 1);
            g_fb[fi] = qid;
        } else {
            float dsum = sqrtf(fmaxf(b0 + sq, 0.0f))
                       + sqrtf(fmaxf(b1 + sq, 0.0f))
                       + sqrtf(fmaxf(b2 + sq, 0.0f));
            g_d[qid] = valid ? dsum : 0.0f;
        }
    }
    grid_sync();

    // ---- phase 6: exact full-scan fallback (rare) ----
    {
        int nfb = __ldcg(&g_fbn);
        for (int fi = bid; fi < nfb; fi += NBLK) {
            int qid = __ldcg(&g_fb[fi]);
            float4 ms = g_q[qid];
            float  msq = fmaxf(ms.w, 0.0f);
            int    mb  = qid >> 14;
            const float* bx = g_sx + mb * NPTS;
            const float* by = g_sy + mb * NPTS;
            const float* bz = g_sz + mb * NPTS;
            const float* bw = g_sw + mb * NPTS;

            float b0 = 3e38f, b1 = 3e38f, b2 = 3e38f;
            int beg = tid * (NPTS / NTHR);
            for (int k = 0; k < NPTS / NTHR; k++) {
                int i = beg + k;
                float r = fmaf(ms.x, bx[i], bw[i]);
                r = fmaf(ms.y, by[i], r);
                r = fmaf(ms.z, bz[i], r);
                top3_insert(r, b0, b1, b2);
            }
            fb3[tid * 3 + 0] = b0;
            fb3[tid * 3 + 1] = b1;
            fb3[tid * 3 + 2] = b2;
            __syncthreads();
            if (tid == 0) {
                float c0 = 3e38f, c1 = 3e38f, c2 = 3e38f;
                for (int i = 0; i < NTHR * 3; i++)
                    top3_insert(fb3[i], c0, c1, c2);
                float dsum = sqrtf(fmaxf(c0 + msq, 0.0f))
                           + sqrtf(fmaxf(c1 + msq, 0.0f))
                           + sqrtf(fmaxf(c2 + msq, 0.0f));
                g_d[qid] = dsum;
            }
            __syncthreads();
        }
    }
    grid_sync();

    // ---- phase 7: deterministic fixed-point reduce ----
    if (bid < 128) {
        int qid = bid * NTHR + tid;               // batch = qid >> 14
        bool valid = (g_q[qid].w >= 0.0f);
        float d = __ldcg(&g_d[qid]);
        long long v = __float2ll_rn(fminf(d, 1e5f) * 4294967296.0f);
#pragma unroll
        for (int o = 16; o; o >>= 1)
            v += __shfl_down_sync(0xffffffffu, v, o);
        int cnt = __popc(__ballot_sync(0xffffffffu, valid));
        if (lane == 0) { wsum[warp] = v; wcnt[warp] = cnt; }
        __syncthreads();
        if (tid == 0) {
            long long vs = 0; int cs = 0;
#pragma unroll
            for (int i = 0; i < NTHR / 32; i++) { vs += wsum[i]; cs += wcnt[i]; }
            g_psum[bid] = vs;
            g_pcnt[bid] = cs;
        }
    }
    grid_sync();

    if (bid == 0) {
        if (tid < 128) {
            rs[tid] = __ldcg(&g_psum[tid]);
            rc[tid] = __ldcg(&g_pcnt[tid]);
        }
        __syncthreads();
        for (int o = 32; o; o >>= 1) {
            if (tid < o) { rs[tid] += rs[tid + o]; rc[tid] += rc[tid + o]; }
            else if (tid >= 64 && tid < 64 + o) {
                rs[tid] += rs[tid + o]; rc[tid] += rc[tid + o];
            }
            __syncthreads();
        }
        if (tid == 0) {
            double S0 = (double)rs[0]  / 4294967296.0;
            double S1 = (double)rs[64] / 4294967296.0;
            float l0 = (float)(S0 / (3.0 * (double)max(rc[0],  1)));
            float l1 = (float)(S1 / (3.0 * (double)max(rc[64], 1)));
            out[0] = 0.5f * (l0 + l1);
        }
    }
}

extern "C" void kernel_launch(void* const* d_in, const int* in_sizes, int n_in,
                              void* d_out, int out_size) {
    const float* src = (const float*)d_in[0];   // source_pc [2,64,2048,3]
    const float* tgt = (const float*)d_in[1];   // target_pc [2,3,64,2048]
    fused_kernel<<<NBLK, NTHR>>>(src, tgt, (float*)d_out);
}